// round 3
// baseline (speedup 1.0000x reference)
#include <cuda_runtime.h>
#include <stdint.h>

// Problem constants
#define BATCH 16
#define LQ 2048
#define LK 2048
#define DH 64

// Tiling: each block = 32 q-rows x full LK, k-tiles of 128. 64 threads,
// 8x8 microtile -> thread grid 4 (ty, q-groups) x 16 (tx, k-groups).
#define BQ 32
#define BK 128
#define NT 64

#define QROW (2*BQ)   // q smem row: each value duplicated -> 64 floats
#define KROW (BK)     // k smem row: 128 floats

#define OUT_ELEMS  ((size_t)BATCH * LQ * DH)   // 2,097,152
#define ATTN_ELEMS ((size_t)BATCH * LQ * LK)   // 67,108,864

// exp(acc * 0.125) entirely on the FMA pipe (no MUFU):
// exp2(acc*0.125*log2e) via magic-number round + degree-5 poly.
__device__ __forceinline__ float fexp_s(float acc) {
    const float C = 0.18033688011112042f;   // 0.125 * log2(e)
    float z = fmaf(acc, C, 12582912.0f);    // round-to-int in low mantissa
    int ish = __float_as_int(z) << 23;      // n << 23 (0x400000 bit shifts out)
    float n = z - 12582912.0f;              // float(n)
    float f = fmaf(acc, C, -n);             // frac in [-0.5, 0.5]
    float p =          1.33335581e-3f;
    p = fmaf(p, f, 9.61812963e-3f);
    p = fmaf(p, f, 5.55041087e-2f);
    p = fmaf(p, f, 2.40226507e-1f);
    p = fmaf(p, f, 6.93147181e-1f);
    p = fmaf(p, f, 1.0f);
    return __int_as_float(__float_as_int(p) + ish);   // p * 2^n
}

// Packed fp32x2 FMA (sm_100+): c.lo += a.lo*b.lo ; c.hi += a.hi*b.hi
#define FFMA2(c, a, b) asm("fma.rn.f32x2 %0, %1, %2, %0;" : "+l"(c) : "l"(a), "l"(b))

__device__ __forceinline__ unsigned long long pack_dup(float x) {
    unsigned long long r;
    unsigned u = __float_as_uint(x);
    asm("mov.b64 %0, {%1, %1};" : "=l"(r) : "r"(u));
    return r;
}

__global__ __launch_bounds__(NT)
void wta_attn2_kernel(const float* __restrict__ q,
                      const float* __restrict__ k,
                      const float* __restrict__ v,
                      float* __restrict__ out,
                      int write_out, int write_attn, long long attn_off)
{
    __shared__ float qs2[DH][QROW];   // [d][2*qrow] value duplicated (for f32x2 a-operand)
    __shared__ float ks [DH][KROW];   // [d][krow]

    const int b   = blockIdx.y;
    const int q0  = blockIdx.x * BQ;
    const int tid = threadIdx.x;
    const int tx  = tid & 15;     // k-group: 8 cols each
    const int ty  = tid >> 4;     // q-group: 8 rows each (0..3)

    const float* qb = q + ((size_t)b * LQ + q0) * DH;
    const float* kb = k + (size_t)b * LK * DH;

    // ---- load q tile (32 x 64), transposed + duplicated into smem ----
    // i = dc*32 + row : lanes hit consecutive rows -> conflict-free-ish STS.64
    {
        #pragma unroll
        for (int it = 0; it < (BQ * DH / 4) / NT; it++) {   // 8 iters
            int i   = tid + it * NT;
            int dc  = i >> 5;        // 0..15
            int row = i & 31;
            float4 w = *(const float4*)(qb + (size_t)row * DH + dc * 4);
            *(unsigned long long*)&qs2[dc*4 + 0][2*row] = pack_dup(w.x);
            *(unsigned long long*)&qs2[dc*4 + 1][2*row] = pack_dup(w.y);
            *(unsigned long long*)&qs2[dc*4 + 2][2*row] = pack_dup(w.z);
            *(unsigned long long*)&qs2[dc*4 + 3][2*row] = pack_dup(w.w);
        }
    }

    // per-thread softmax state for 8 q-rows
    float m[8], sum[8];
    int   idx[8];
    #pragma unroll
    for (int i = 0; i < 8; i++) { m[i] = -1e30f; sum[i] = 0.0f; idx[i] = 0; }

    float4* az = 0;
    if (write_attn)
        az = (float4*)(out + attn_off + ((size_t)b * LQ + q0) * LK);

    for (int kt = 0; kt < LK; kt += BK) {
        __syncthreads();

        // ---- load k tile (128 x 64), transposed ----
        #pragma unroll 4
        for (int it = 0; it < (BK * DH / 4) / NT; it++) {   // 32 iters
            int i  = tid + it * NT;
            int dc = i >> 7;          // 0..15
            int kr = i & 127;
            float4 w = *(const float4*)(kb + (size_t)(kt + kr) * DH + dc * 4);
            ks[dc*4 + 0][kr] = w.x;
            ks[dc*4 + 1][kr] = w.y;
            ks[dc*4 + 2][kr] = w.z;
            ks[dc*4 + 3][kr] = w.w;
        }

        // ---- interleaved zero-fill of this block's attn slice chunk ----
        if (write_attn) {
            float4* azc = az + (kt >> 7) * (BQ * BK / 4);   // 1024 float4 per tile
            #pragma unroll
            for (int j = 0; j < 16; j++)
                azc[tid + j * NT] = make_float4(0.f, 0.f, 0.f, 0.f);
        }
        __syncthreads();

        // ---- 8x8 microtile, f32x2-packed accumulation over j ----
        unsigned long long acc[8][4];
        #pragma unroll
        for (int i = 0; i < 8; i++)
            #pragma unroll
            for (int jp = 0; jp < 4; jp++) acc[i][jp] = 0ull;

        #pragma unroll 8
        for (int d = 0; d < DH; d++) {
            const ulonglong2* bp = (const ulonglong2*)&ks[d][tx * 8];
            ulonglong2 bv0 = bp[0];                    // (b0,b1) (b2,b3)
            ulonglong2 bv1 = bp[1];                    // (b4,b5) (b6,b7)
            const ulonglong2* ap = (const ulonglong2*)&qs2[d][ty * 16];
            ulonglong2 av0 = ap[0], av1 = ap[1], av2 = ap[2], av3 = ap[3];

            unsigned long long A[8] = {av0.x, av0.y, av1.x, av1.y,
                                       av2.x, av2.y, av3.x, av3.y};
            unsigned long long B[4] = {bv0.x, bv0.y, bv1.x, bv1.y};
            #pragma unroll
            for (int i = 0; i < 8; i++) {
                #pragma unroll
                for (int jp = 0; jp < 4; jp++)
                    FFMA2(acc[i][jp], A[i], B[jp]);
            }
        }

        // ---- per-tile softmax partials (FMA-pipe exp, raw-acc argmax) ----
        const int kbase = kt + tx * 8;
        #pragma unroll
        for (int i = 0; i < 8; i++) {
            float s = sum[i];
            #pragma unroll
            for (int jp = 0; jp < 4; jp++) {
                float s0 = __uint_as_float((unsigned)(acc[i][jp] & 0xffffffffu));
                float s1 = __uint_as_float((unsigned)(acc[i][jp] >> 32));
                if (s0 > m[i]) { m[i] = s0; idx[i] = kbase + jp*2; }
                if (s1 > m[i]) { m[i] = s1; idx[i] = kbase + jp*2 + 1; }
                s += fexp_s(s0) + fexp_s(s1);
            }
            sum[i] = s;
        }
    }

    // ---- reduce (m, idx, sum) across the 16 lanes sharing each q-row ----
    #pragma unroll
    for (int i = 0; i < 8; i++) {
        #pragma unroll
        for (int off = 8; off > 0; off >>= 1) {
            float om = __shfl_xor_sync(0xffffffffu, m[i],   off, 16);
            int   oi = __shfl_xor_sync(0xffffffffu, idx[i], off, 16);
            float os = __shfl_xor_sync(0xffffffffu, sum[i], off, 16);
            sum[i] += os;
            if (om > m[i] || (om == m[i] && oi < idx[i])) { m[i] = om; idx[i] = oi; }
        }
    }

    __syncthreads();   // all zero-fill stores ordered before winner scatter

    // ---- scatter winners into attn ----
    if (write_attn && tx == 0) {
        #pragma unroll
        for (int i = 0; i < 8; i++) {
            float p = fexp_s(m[i]) / sum[i];
            out[attn_off + ((size_t)b * LQ + q0 + ty * 8 + i) * LK + idx[i]] = p;
        }
    }

    // ---- dense output: out[b,q,:] = p * v[b, argmax, :] ----
    if (write_out) {
        #pragma unroll
        for (int i = 0; i < 8; i++) {
            float p = fexp_s(m[i]) / sum[i];
            const float4 vv = *(const float4*)(v + ((size_t)b * LK + idx[i]) * DH + tx * 4);
            float4 o;
            o.x = p * vv.x; o.y = p * vv.y; o.z = p * vv.z; o.w = p * vv.w;
            *(float4*)(out + ((size_t)b * LQ + q0 + ty * 8 + i) * DH + tx * 4) = o;
        }
    }
}

extern "C" void kernel_launch(void* const* d_in, const int* in_sizes, int n_in,
                              void* d_out, int out_size)
{
    const float* q = (const float*)d_in[0];
    const float* k = (const float*)d_in[1];
    const float* v = (const float*)d_in[2];
    float* out = (float*)d_out;

    int wout = 0, wattn = 0;
    long long aoff = 0;
    size_t osz = (size_t)out_size;
    if (osz == OUT_ELEMS + ATTN_ELEMS) { wout = 1; wattn = 1; aoff = (long long)OUT_ELEMS; }
    else if (osz == ATTN_ELEMS)        { wattn = 1; aoff = 0; }
    else                               { wout = 1; }

    dim3 grid(LQ / BQ, BATCH);
    wta_attn2_kernel<<<grid, NT>>>(q, k, v, out, wout, wattn, aoff);
}

// round 4
// speedup vs baseline: 2.4835x; 2.4835x over previous
#include <cuda_runtime.h>
#include <stdint.h>

// Problem constants
#define BATCH 16
#define LQ 2048
#define LK 2048
#define DH 64

// Tiling: block = 64 q-rows x full LK, k-tiles of 128. 128 threads,
// 8x8 microtile: ty (0..7) picks q rows {ty*4+i, 32+ty*4+i},
//                tx (0..15) picks k cols {tx*4+j, 64+tx*4+j}.
#define BQ 64
#define BK 128
#define NT 128

#define OUT_ELEMS  ((size_t)BATCH * LQ * DH)   // 2,097,152
#define ATTN_ELEMS ((size_t)BATCH * LQ * LK)   // 67,108,864

// single-MUFU exp2
__device__ __forceinline__ float ex2a(float x) {
    float r; asm("ex2.approx.ftz.f32 %0, %1;" : "=f"(r) : "f"(x)); return r;
}

__global__ __launch_bounds__(NT, 4)
void wta_attn4_kernel(const float* __restrict__ q,
                      const float* __restrict__ k,
                      const float* __restrict__ v,
                      float* __restrict__ out,
                      int write_out, int write_attn, long long attn_off)
{
    __shared__ float qs[DH][BQ];            // 16 KB static  [d][qrow]
    extern __shared__ float ksm[];          // 32 KB dynamic [d][krow]
    float (*ks)[BK] = (float(*)[BK])ksm;

    const int b   = blockIdx.y;
    const int q0  = blockIdx.x * BQ;
    const int tid = threadIdx.x;
    const int tx  = tid & 15;     // k-group
    const int ty  = tid >> 4;     // q-group (0..7)

    const float* qb = q + ((size_t)b * LQ + q0) * DH;
    const float* kb = k + (size_t)b * LK * DH;

    // ---- q tile (64 x 64): strided LDG, conflict-free transposed STS ----
    {
        const int row = tid & 63;
        const int dcb = tid >> 6;               // 0..1
        #pragma unroll
        for (int it = 0; it < 8; it++) {
            int dc = (it * 2 + dcb) * 4;
            float4 w = *(const float4*)(qb + (size_t)row * DH + dc);
            qs[dc + 0][row] = w.x; qs[dc + 1][row] = w.y;
            qs[dc + 2][row] = w.z; qs[dc + 3][row] = w.w;
        }
    }

    // per-thread softmax state for 8 q-rows
    float m[8], sum[8];
    int   idx[8];
    #pragma unroll
    for (int i = 0; i < 8; i++) { m[i] = -1e30f; sum[i] = 0.0f; idx[i] = 0; }

    const float C = 0.18033688011112042f;   // 0.125 * log2(e)

    float4* az = 0;
    if (write_attn)
        az = (float4*)(out + attn_off + ((size_t)b * LQ + q0) * LK);

    for (int kt = 0; kt < LK; kt += BK) {
        __syncthreads();

        // ---- k tile (128 x 64): strided LDG, conflict-free transposed STS ----
        {
            const int krow = tid;               // 0..127
            const float* kp = kb + (size_t)(kt + krow) * DH;
            #pragma unroll 4
            for (int it = 0; it < 16; it++) {
                int dc = it * 4;
                float4 w = *(const float4*)(kp + dc);
                ks[dc + 0][krow] = w.x; ks[dc + 1][krow] = w.y;
                ks[dc + 2][krow] = w.z; ks[dc + 3][krow] = w.w;
            }
        }

        // ---- interleaved zero-fill of this block's attn chunk (64 x 128) ----
        if (write_attn) {
            float4* azc = az + (kt >> 7) * (BQ * BK / 4);   // 2048 float4 / tile
            #pragma unroll
            for (int j = 0; j < 16; j++)
                azc[tid + j * NT] = make_float4(0.f, 0.f, 0.f, 0.f);
        }
        __syncthreads();

        // ---- 8x8 microtile dot products over d ----
        float acc[8][8];
        #pragma unroll
        for (int i = 0; i < 8; i++)
            #pragma unroll
            for (int j = 0; j < 8; j++) acc[i][j] = 0.0f;

        #pragma unroll 4
        for (int d = 0; d < DH; d++) {
            float4 a0 = *(const float4*)&qs[d][ty * 4];
            float4 a1 = *(const float4*)&qs[d][32 + ty * 4];
            float4 b0 = *(const float4*)&ks[d][tx * 4];
            float4 b1 = *(const float4*)&ks[d][64 + tx * 4];
            float A[8] = {a0.x, a0.y, a0.z, a0.w, a1.x, a1.y, a1.z, a1.w};
            float B[8] = {b0.x, b0.y, b0.z, b0.w, b1.x, b1.y, b1.z, b1.w};
            #pragma unroll
            for (int i = 0; i < 8; i++)
                #pragma unroll
                for (int j = 0; j < 8; j++)
                    acc[i][j] += A[i] * B[j];
        }

        // ---- softmax partials: argmax on raw acc (scale is monotone), MUFU exp ----
        #pragma unroll
        for (int i = 0; i < 8; i++) {
            float s = sum[i];
            #pragma unroll
            for (int j = 0; j < 8; j++) {
                float a = acc[i][j];
                int kg = kt + ((j < 4) ? (tx * 4 + j) : (64 + tx * 4 + (j - 4)));
                if (a > m[i]) { m[i] = a; idx[i] = kg; }
                s += ex2a(a * C);
            }
            sum[i] = s;
        }
    }

    // ---- butterfly reduce (m, idx, sum) across the 16 lanes per q-row ----
    #pragma unroll
    for (int i = 0; i < 8; i++) {
        #pragma unroll
        for (int off = 8; off > 0; off >>= 1) {
            float om = __shfl_xor_sync(0xffffffffu, m[i],   off, 16);
            int   oi = __shfl_xor_sync(0xffffffffu, idx[i], off, 16);
            float os = __shfl_xor_sync(0xffffffffu, sum[i], off, 16);
            sum[i] += os;
            if (om > m[i] || (om == m[i] && oi < idx[i])) { m[i] = om; idx[i] = oi; }
        }
    }

    __syncthreads();   // order zero-fill stores before winner scatter

    // ---- scatter winners into attn ----
    if (write_attn && tx == 0) {
        #pragma unroll
        for (int i = 0; i < 8; i++) {
            int row = (i < 4) ? (ty * 4 + i) : (32 + ty * 4 + (i - 4));
            float p = ex2a(m[i] * C) / sum[i];
            out[attn_off + ((size_t)b * LQ + q0 + row) * LK + idx[i]] = p;
        }
    }

    // ---- dense output: out[b,q,:] = p * v[b, argmax, :] (all 16 lanes/row) ----
    if (write_out) {
        #pragma unroll
        for (int i = 0; i < 8; i++) {
            int row = (i < 4) ? (ty * 4 + i) : (32 + ty * 4 + (i - 4));
            float p = ex2a(m[i] * C) / sum[i];
            const float4 vv = *(const float4*)(v + ((size_t)b * LK + idx[i]) * DH + tx * 4);
            float4 o;
            o.x = p * vv.x; o.y = p * vv.y; o.z = p * vv.z; o.w = p * vv.w;
            *(float4*)(out + ((size_t)b * LQ + q0 + row) * DH + tx * 4) = o;
        }
    }
}

extern "C" void kernel_launch(void* const* d_in, const int* in_sizes, int n_in,
                              void* d_out, int out_size)
{
    const float* q = (const float*)d_in[0];
    const float* k = (const float*)d_in[1];
    const float* v = (const float*)d_in[2];
    float* out = (float*)d_out;

    int wout = 0, wattn = 0;
    long long aoff = 0;
    size_t osz = (size_t)out_size;
    if (osz == OUT_ELEMS + ATTN_ELEMS) { wout = 1; wattn = 1; aoff = (long long)OUT_ELEMS; }
    else if (osz == ATTN_ELEMS)        { wattn = 1; aoff = 0; }
    else                               { wout = 1; }

    dim3 grid(LQ / BQ, BATCH);
    wta_attn4_kernel<<<grid, NT, (size_t)DH * BK * sizeof(float)>>>(
        q, k, v, out, wout, wattn, aoff);
}